// round 8
// baseline (speedup 1.0000x reference)
#include <cuda_runtime.h>
#include <cuda_fp16.h>
#include <cstdint>
#include <cstddef>

#define BATCH   8192
#define IN_DIM  4096
#define HID     16384
#define KSEL    64

// -------- scratch (allocation-free: __device__ globals) --------
__device__ __half g_wdecT[(size_t)HID * IN_DIM];     // W_dec^T in fp16 [HID, IN_DIM]
__device__ float  g_vals[BATCH * KSEL];
__device__ int    g_idx [BATCH * KSEL];
__device__ __half g_xh[(size_t)BATCH * IN_DIM];      // fp16(x)
__device__ __half g_wh[(size_t)HID * IN_DIM];        // fp16(W_enc)

// ============================================================================
// fp32 -> fp16 conversion
// ============================================================================
__global__ __launch_bounds__(256) void to_half_kernel(
    const float* __restrict__ src, __half* __restrict__ dst, size_t n4)
{
    size_t i = (size_t)blockIdx.x * 256 + threadIdx.x;
    if (i >= n4) return;
    float4 v = ((const float4*)src)[i];
    __half2* d = (__half2*)dst;
    d[2 * i]     = __floats2half2_rn(v.x, v.y);
    d[2 * i + 1] = __floats2half2_rn(v.z, v.w);
}

// ============================================================================
// transpose W_dec [IN_DIM, HID] -> g_wdecT (fp16) [HID, IN_DIM]
// ============================================================================
__global__ void wdec_transpose(const float* __restrict__ W)
{
    __shared__ float tile[32][33];
    int h0 = blockIdx.x * 32;
    int d0 = blockIdx.y * 32;
    int tx = threadIdx.x, ty = threadIdx.y;
#pragma unroll
    for (int r = 0; r < 32; r += 8)
        tile[ty + r][tx] = W[(size_t)(d0 + ty + r) * HID + (h0 + tx)];
    __syncthreads();
#pragma unroll
    for (int r = 0; r < 32; r += 8)
        g_wdecT[(size_t)(h0 + ty + r) * IN_DIM + (d0 + tx)] =
            __float2half_rn(tile[tx][ty + r]);
}

// ============================================================================
// Encoder GEMM: fp16 mma.sync (HMMA), fp32 accumulate  (unchanged from R7)
// ============================================================================
#define GBM 128
#define GBN 256
#define GBK 64
#define NSTAGE 3
#define ROWB 144
#define A_ST_B (GBM * ROWB)
#define B_ST_B (GBN * ROWB)
#define STG_B  (A_ST_B + B_ST_B)
#define GEMM_SMEM (NSTAGE * STG_B)
#define K_ITERS (IN_DIM / GBK)
#define GEMM_THREADS 512

__device__ __forceinline__ uint32_t smem_u32(const void* p) {
    uint32_t a;
    asm("{ .reg .u64 t; cvta.to.shared.u64 t, %1; cvt.u32.u64 %0, t; }" : "=r"(a) : "l"(p));
    return a;
}
#define CP_ASYNC16(dst, src) \
    asm volatile("cp.async.cg.shared.global [%0], [%1], 16;" :: "r"(dst), "l"(src))
#define CP_COMMIT() asm volatile("cp.async.commit_group;" ::: "memory")
#define CP_WAIT1()  asm volatile("cp.async.wait_group 1;" ::: "memory")

#define LDSM_X4(r0, r1, r2, r3, addr) \
    asm volatile("ldmatrix.sync.aligned.m8n8.x4.shared.b16 {%0,%1,%2,%3}, [%4];" \
                 : "=r"(r0), "=r"(r1), "=r"(r2), "=r"(r3) : "r"(addr))

#define MMA16816(d, a, b0, b1) \
    asm volatile("mma.sync.aligned.m16n8k16.row.col.f32.f16.f16.f32 " \
                 "{%0,%1,%2,%3}, {%4,%5,%6,%7}, {%8,%9}, {%0,%1,%2,%3};" \
                 : "+f"((d)[0]), "+f"((d)[1]), "+f"((d)[2]), "+f"((d)[3]) \
                 : "r"((a)[0]), "r"((a)[1]), "r"((a)[2]), "r"((a)[3]), \
                   "r"(b0), "r"(b1))

__device__ __forceinline__ void gemm_load_stage(uint32_t sbase, int stage, int k0,
                                                int m0, int n0, int tid)
{
    uint32_t sb = sbase + stage * STG_B;
#pragma unroll
    for (int t = 0; t < 2; t++) {
        int i = tid + t * GEMM_THREADS;
        int row = i >> 3, c = i & 7;
        const __half* src = g_xh + (size_t)(m0 + row) * IN_DIM + k0 + c * 8;
        CP_ASYNC16(sb + row * ROWB + c * 16, src);
    }
    uint32_t sbB = sb + A_ST_B;
#pragma unroll
    for (int t = 0; t < 4; t++) {
        int i = tid + t * GEMM_THREADS;
        int row = i >> 3, c = i & 7;
        const __half* src = g_wh + (size_t)(n0 + row) * IN_DIM + k0 + c * 8;
        CP_ASYNC16(sbB + row * ROWB + c * 16, src);
    }
}

__global__ __launch_bounds__(GEMM_THREADS, 1) void encoder_gemm_hmma(
    const float* __restrict__ bias, float* __restrict__ out_sf)
{
    extern __shared__ __align__(128) char smem[];
    uint32_t sbase = smem_u32(smem);
    const int tid  = threadIdx.x;
    const int lane = tid & 31;
    const int wid  = tid >> 5;
    const int warp_m = wid & 1;
    const int warp_n = wid >> 1;

    int pid = blockIdx.x;
    int nb = (pid >> 3) & 63;
    int mb = (pid & 7) | ((pid >> 9) << 3);
    int m0 = mb * GBM, n0 = nb * GBN;

    const int g = lane >> 3;
    const int rA = warp_m * 64 + ((g & 1) << 3) + (lane & 7);
    const int cA = (g >> 1) << 4;
    const int rB = warp_n * 32 + ((g >> 1) << 3) + (lane & 7);
    const int cB = (g & 1) << 4;

    float acc[4][4][4];
#pragma unroll
    for (int i = 0; i < 4; i++)
#pragma unroll
        for (int j = 0; j < 4; j++)
#pragma unroll
            for (int q = 0; q < 4; q++) acc[i][j][q] = 0.0f;

    gemm_load_stage(sbase, 0, 0, m0, n0, tid); CP_COMMIT();
    gemm_load_stage(sbase, 1, GBK, m0, n0, tid); CP_COMMIT();

    for (int it = 0; it < K_ITERS; it++) {
        int cur = it % 3;
        CP_WAIT1();
        __syncthreads();

        if (it + 2 < K_ITERS)
            gemm_load_stage(sbase, (it + 2) % 3, (it + 2) * GBK, m0, n0, tid);
        CP_COMMIT();

        uint32_t aST = sbase + cur * STG_B;
        uint32_t bST = aST + A_ST_B;

#pragma unroll
        for (int ks = 0; ks < 4; ks++) {
            uint32_t koff = (uint32_t)(ks * 32);
            uint32_t af[4][4], bf[2][4];
#pragma unroll
            for (int mf = 0; mf < 4; mf++) {
                uint32_t ad = aST + (uint32_t)((rA + mf * 16) * ROWB + cA) + koff;
                LDSM_X4(af[mf][0], af[mf][1], af[mf][2], af[mf][3], ad);
            }
#pragma unroll
            for (int nf = 0; nf < 2; nf++) {
                uint32_t bd = bST + (uint32_t)((rB + nf * 16) * ROWB + cB) + koff;
                LDSM_X4(bf[nf][0], bf[nf][1], bf[nf][2], bf[nf][3], bd);
            }
#pragma unroll
            for (int mf = 0; mf < 4; mf++)
#pragma unroll
                for (int nf = 0; nf < 2; nf++) {
                    MMA16816(acc[mf][nf * 2],     af[mf], bf[nf][0], bf[nf][1]);
                    MMA16816(acc[mf][nf * 2 + 1], af[mf], bf[nf][2], bf[nf][3]);
                }
        }
    }

    int rbase = m0 + warp_m * 64 + (lane >> 2);
    int cbase = n0 + warp_n * 32 + ((lane & 3) << 1);
#pragma unroll
    for (int mf = 0; mf < 4; mf++) {
#pragma unroll
        for (int nf = 0; nf < 4; nf++) {
            int col = cbase + nf * 8;
            float b0 = __ldg(&bias[col]);
            float b1 = __ldg(&bias[col + 1]);
            int r0 = rbase + mf * 16;
            float2 v0, v1;
            v0.x = fmaxf(acc[mf][nf][0] + b0, 0.0f);
            v0.y = fmaxf(acc[mf][nf][1] + b1, 0.0f);
            v1.x = fmaxf(acc[mf][nf][2] + b0, 0.0f);
            v1.y = fmaxf(acc[mf][nf][3] + b1, 0.0f);
            *(float2*)(out_sf + (size_t)r0 * HID + col)       = v0;
            *(float2*)(out_sf + (size_t)(r0 + 8) * HID + col) = v1;
        }
    }
}

// ============================================================================
// top-k (k=64): single-pass histogram bracket + exact boundary refinement
//   512 threads/row. Bracket [B_lo,B_hi) of the approx 64th value from one
//   512-bin histogram over [2,8); zone = [B_lo-2e, B_hi+2e] gets exact
//   compensated-fp32 dots; selection ranks refined values (index tiebreak).
// ============================================================================
#define TOPK_THREADS 512
#define NBINS 1024
#define TOPK_SMEM_BYTES ((HID + NBINS + HID / 32) * 4)
#define ERRB 3e-3f
#define ZCAP 128

__device__ __forceinline__ float refine_dot_warp(const float* __restrict__ xr,
                                                 const float* __restrict__ wr,
                                                 float b, int lane)
{
    float s = 0.f, c = 0.f;
    for (int t = 0; t < 16; t++) {
        int base = t * 256 + lane;
        float r = xr[base] * wr[base];
#pragma unroll
        for (int j = 1; j < 8; j++)
            r = fmaf(xr[base + 32 * j], wr[base + 32 * j], r);
        float tt = s + r;
        float z = tt - s;
        float e = (s - (tt - z)) + (r - z);
        c += e; s = tt;
    }
#pragma unroll
    for (int off = 16; off; off >>= 1) {
        float s2 = __shfl_down_sync(0xffffffffu, s, off);
        float c2 = __shfl_down_sync(0xffffffffu, c, off);
        float tt = s + s2;
        float z = tt - s;
        float e = (s - (tt - z)) + (s2 - z);
        c += c2 + e; s = tt;
    }
    float d = s + c;
    return fmaxf(d + b, 0.0f);
}

// warp 0: scan bins from top, find bin where cumulative (incl. base) reaches 64
__device__ __forceinline__ int scan_bins_top(const uint32_t* hist, int top,
                                             int base, int lane)
{
    int dbin = -1;
    int nrounds = (top + 31) / 32;
    for (int r = 0; r < nrounds; r++) {
        int bin = top - 1 - (r * 32 + lane);
        int h = (bin >= 0) ? (int)hist[bin] : 0;
        int pre = h;
#pragma unroll
        for (int off = 1; off < 32; off <<= 1) {
            int t = __shfl_up_sync(0xffffffffu, pre, off);
            if (lane >= off) pre += t;
        }
        int cum = base + pre;
        unsigned bal = __ballot_sync(0xffffffffu, (cum >= KSEL) && (bin >= 0));
        if (bal) {
            int l0 = __ffs(bal) - 1;
            dbin = top - 1 - (r * 32 + l0);
            break;
        }
        base += __shfl_sync(0xffffffffu, pre, 31);
    }
    return dbin;
}

__global__ __launch_bounds__(TOPK_THREADS) void topk_kernel(
    float* __restrict__ out_sf,
    const float* __restrict__ x,
    const float* __restrict__ W,
    const float* __restrict__ bias)
{
    extern __shared__ __align__(128) char shraw[];
    uint32_t* sbits = (uint32_t*)shraw;        // HID
    uint32_t* hist  = sbits + HID;             // NBINS
    uint32_t* keep  = sbits + HID + NBINS;     // HID/32
    __shared__ int s_big, s_nhi, s_nzone, s_dbin, s_mode;
    __shared__ int   s_zidx[ZCAP];
    __shared__ float s_zval[ZCAP];
    __shared__ unsigned char s_keepz[ZCAP];

    int row = blockIdx.x;
    int tid = threadIdx.x;
    int wid = tid >> 5, lane = tid & 31;
    float* orow = out_sf + (size_t)row * HID;

    // zero hist + init scalars
    hist[tid] = 0; hist[tid + TOPK_THREADS] = 0;
    if (tid == 0) { s_big = 0; s_nhi = 0; s_nzone = 0; s_dbin = -1; s_mode = 0; }
    __syncthreads();

    // load row + mode-A histogram (values in [2,8) -> bins on bits[30:15])
    int mybig = 0;
#pragma unroll
    for (int t = 0; t < 8; t++) {
        int i4 = tid + t * TOPK_THREADS;
        float4 v4 = ((const float4*)orow)[i4];
        float vv[4] = {v4.x, v4.y, v4.z, v4.w};
#pragma unroll
        for (int c = 0; c < 4; c++) {
            uint32_t u = __float_as_uint(vv[c]);
            if (u == 0x80000000u) u = 0u;
            sbits[i4 * 4 + c] = u;
            float f = __uint_as_float(u);
            if (f >= 8.0f) mybig++;
            else if (f >= 2.0f) atomicAdd(&hist[(u >> 15) - 0x8000u], 1u);
        }
    }
#pragma unroll
    for (int off = 16; off; off >>= 1) mybig += __shfl_down_sync(0xffffffffu, mybig, off);
    if (lane == 0 && mybig) atomicAdd(&s_big, mybig);
    __syncthreads();

    // bracket scan, mode A
    if (wid == 0) {
        int d = scan_bins_top(hist, 512, s_big, lane);
        if (lane == 0) { s_dbin = d; if (d >= 0) s_mode = 1; }
    }
    __syncthreads();

    if (s_mode == 0) {
        // mode B: rare — histogram [0.25, 8) on bits[30:16]
        hist[tid] = 0; hist[tid + TOPK_THREADS] = 0;
        __syncthreads();
        for (int i = tid; i < HID; i += TOPK_THREADS) {
            float f = __uint_as_float(sbits[i]);
            if (f >= 0.25f && f < 8.0f)
                atomicAdd(&hist[(sbits[i] >> 16) - 0x3E80u], 1u);
        }
        __syncthreads();
        if (wid == 0) {
            int d = scan_bins_top(hist, 640, s_big, lane);
            if (lane == 0) { s_dbin = d; if (d >= 0) s_mode = 2; else s_mode = 3; }
        }
        __syncthreads();
    }

    // bracket edges
    float B_lo, B_hi;
    if (s_mode == 1) {
        B_lo = __uint_as_float((uint32_t)(0x8000u + s_dbin) << 15);
        B_hi = __uint_as_float((uint32_t)(0x8000u + s_dbin + 1) << 15);
    } else if (s_mode == 2) {
        B_lo = __uint_as_float((uint32_t)(0x3E80u + s_dbin) << 16);
        B_hi = __uint_as_float((uint32_t)(0x3E80u + s_dbin + 1) << 16);
    } else {  // mode C: degenerate (essentially never)
        B_lo = 0.0f; B_hi = 0.25f;
    }
    float Thi  = B_hi + 2.0f * ERRB;
    float Tlo  = B_lo - 2.0f * ERRB;
    float Tlo2 = Tlo - 2.0f * ERRB;

    // classify: nhi = count(> Thi); zone = (0, Thi] ∩ [Tlo, ...]
    for (int i = tid; i < HID; i += TOPK_THREADS) {
        float f = __uint_as_float(sbits[i]);
        if (f > Thi) atomicAdd(&s_nhi, 1);
        else if (f > 0.0f && f >= Tlo) {
            int p = atomicAdd(&s_nzone, 1);
            if (p < ZCAP) s_zidx[p] = i;
        }
    }
    __syncthreads();

    int nhi  = s_nhi;
    int nzr  = s_nzone;
    bool ovf = (nzr > ZCAP);
    int nz   = ovf ? ZCAP : nzr;
    int need = KSEL - nhi;

    // init zone values with approx
    if (tid < nz) s_zval[tid] = __uint_as_float(sbits[s_zidx[tid]]);
    __syncthreads();

    // exact refinement when selection matters
    bool did_refine = (!ovf && nz != need && nz > 0 && need > 0);
    if (did_refine) {
        const float* xr = x + (size_t)row * IN_DIM;
        for (int j = wid; j < nz; j += (TOPK_THREADS / 32)) {
            int h = s_zidx[j];
            float v = refine_dot_warp(xr, W + (size_t)h * IN_DIM, __ldg(&bias[h]), lane);
            if (lane == 0) s_zval[j] = v;
        }
    }
    __syncthreads();

    // parallel rank selection among zone (exact top-`need`, index tiebreak)
    if (tid < nz) {
        bool km;
        if (!ovf && nz == need) km = true;
        else if (need <= 0) km = false;
        else {
            float mv = s_zval[tid]; int mi = s_zidx[tid];
            int better = 0;
            for (int j = 0; j < nz; j++) {
                if (j == tid) continue;
                if (s_zval[j] > mv || (s_zval[j] == mv && s_zidx[j] < mi)) better++;
            }
            km = (better < need);
        }
        s_keepz[tid] = km ? 1 : 0;
    }
    __syncthreads();

    // kept zone elements carry refined values
    if (did_refine && tid < nz && s_keepz[tid])
        sbits[s_zidx[tid]] = __float_as_uint(s_zval[tid]);
    __syncthreads();

    // output + keep bitmap: thread t owns word t (elements [t*32, t*32+32))
    {
        uint32_t m = 0;
        int base = tid * 32;
#pragma unroll 4
        for (int b = 0; b < 32; b++) {
            int i = base + b;
            uint32_t u = sbits[i];
            float f = __uint_as_float(u);
            bool kp = false;
            if (f > Thi) kp = true;
            else if (f > 0.0f && f >= Tlo2) {
                for (int j = 0; j < nz; j++)
                    if (s_zidx[j] == i) { kp = (s_keepz[j] != 0); break; }
            }
            if (kp) { m |= (1u << b); orow[i] = f; }
            else if (u != 0u) orow[i] = 0.0f;
        }
        keep[tid] = m;
    }
    __syncthreads();

    // deterministic compaction (warp 0, index order)
    if (tid < 32) {
        int cnt = 0;
        for (int base = 0; base < HID; base += 32) {
            uint32_t m = keep[base >> 5];
            bool kp = (m >> lane) & 1u;
            int r = __popc(m & ((1u << lane) - 1u));
            if (kp && cnt + r < KSEL) {
                g_vals[row * KSEL + cnt + r] = __uint_as_float(sbits[base + lane]);
                g_idx [row * KSEL + cnt + r] = base + lane;
            }
            cnt += __popc(m);
        }
    }
}

// ============================================================================
// sparse decode  recon[b,:] = sum_j v_j * W_dec^T[h_j, :]  (fp16 weights)
// ============================================================================
__global__ __launch_bounds__(256) void decoder_kernel(float* __restrict__ out_rec)
{
    int row = blockIdx.x;
    int tid = threadIdx.x;
    __shared__ float sv[KSEL];
    __shared__ int   si[KSEL];
    if (tid < KSEL) { sv[tid] = g_vals[row * KSEL + tid]; si[tid] = g_idx[row * KSEL + tid]; }
    __syncthreads();

    float acc[16];
#pragma unroll
    for (int q = 0; q < 16; q++) acc[q] = 0.0f;

    for (int j = 0; j < KSEL; j++) {
        float v = sv[j];
        const uint4* wp = (const uint4*)(g_wdecT + (size_t)si[j] * IN_DIM);
#pragma unroll
        for (int w = 0; w < 2; w++) {
            uint4 t = wp[tid + w * 256];
            float2 f0 = __half22float2(*(__half2*)&t.x);
            float2 f1 = __half22float2(*(__half2*)&t.y);
            float2 f2 = __half22float2(*(__half2*)&t.z);
            float2 f3 = __half22float2(*(__half2*)&t.w);
            acc[w*8+0] = fmaf(v, f0.x, acc[w*8+0]);
            acc[w*8+1] = fmaf(v, f0.y, acc[w*8+1]);
            acc[w*8+2] = fmaf(v, f1.x, acc[w*8+2]);
            acc[w*8+3] = fmaf(v, f1.y, acc[w*8+3]);
            acc[w*8+4] = fmaf(v, f2.x, acc[w*8+4]);
            acc[w*8+5] = fmaf(v, f2.y, acc[w*8+5]);
            acc[w*8+6] = fmaf(v, f3.x, acc[w*8+6]);
            acc[w*8+7] = fmaf(v, f3.y, acc[w*8+7]);
        }
    }
    float* op = out_rec + (size_t)row * IN_DIM;
#pragma unroll
    for (int w = 0; w < 2; w++) {
        *(float4*)(op + (tid + w * 256) * 8)     = *(float4*)(&acc[w*8]);
        *(float4*)(op + (tid + w * 256) * 8 + 4) = *(float4*)(&acc[w*8+4]);
    }
}

// ============================================================================
// launch
// ============================================================================
extern "C" void kernel_launch(void* const* d_in, const int* in_sizes, int n_in,
                              void* d_out, int out_size)
{
    const float* x     = (const float*)d_in[0];
    const float* W_enc = (const float*)d_in[1];
    const float* b_enc = (const float*)d_in[2];
    const float* W_dec = (const float*)d_in[3];

    float* out_sf  = (float*)d_out;
    float* out_rec = out_sf + (size_t)BATCH * HID;

    __half *xh, *wh;
    cudaGetSymbolAddress((void**)&xh, g_xh);
    cudaGetSymbolAddress((void**)&wh, g_wh);

    // 1) fp16 conversions
    size_t nx4 = (size_t)BATCH * IN_DIM / 4;
    size_t nw4 = (size_t)HID * IN_DIM / 4;
    to_half_kernel<<<(unsigned)(nx4 / 256), 256>>>(x, xh, nx4);
    to_half_kernel<<<(unsigned)(nw4 / 256), 256>>>(W_enc, wh, nw4);

    // 2) transpose W_dec -> fp16
    wdec_transpose<<<dim3(HID / 32, IN_DIM / 32), dim3(32, 8)>>>(W_dec);

    // 3) approx encoder GEMM (HMMA fp16, fp32 accum) -> out_sf (dense)
    cudaFuncSetAttribute(encoder_gemm_hmma, cudaFuncAttributeMaxDynamicSharedMemorySize,
                         GEMM_SMEM);
    encoder_gemm_hmma<<<(HID / GBN) * (BATCH / GBM), GEMM_THREADS, GEMM_SMEM>>>(b_enc, out_sf);

    // 4) top-k: histogram bracket + exact boundary refinement (in-place)
    cudaFuncSetAttribute(topk_kernel, cudaFuncAttributeMaxDynamicSharedMemorySize,
                         TOPK_SMEM_BYTES);
    topk_kernel<<<BATCH, TOPK_THREADS, TOPK_SMEM_BYTES>>>(out_sf, x, W_enc, b_enc);

    // 5) sparse decode (fp16 weights)
    decoder_kernel<<<BATCH, 256>>>(out_rec);
}

// round 9
// speedup vs baseline: 1.0894x; 1.0894x over previous
#include <cuda_runtime.h>
#include <cuda_fp16.h>
#include <cstdint>
#include <cstddef>

#define BATCH   8192
#define IN_DIM  4096
#define HID     16384
#define KSEL    64

// -------- scratch (allocation-free: __device__ globals) --------
__device__ __half g_wdecT[(size_t)HID * IN_DIM];     // W_dec^T in fp16 [HID, IN_DIM]
__device__ float  g_vals[BATCH * KSEL];
__device__ int    g_idx [BATCH * KSEL];
__device__ __half g_xh[(size_t)BATCH * IN_DIM];      // fp16(x)
__device__ __half g_wh[(size_t)HID * IN_DIM];        // fp16(W_enc)

// ============================================================================
// fp32 -> fp16 conversion
// ============================================================================
__global__ __launch_bounds__(256) void to_half_kernel(
    const float* __restrict__ src, __half* __restrict__ dst, size_t n4)
{
    size_t i = (size_t)blockIdx.x * 256 + threadIdx.x;
    if (i >= n4) return;
    float4 v = ((const float4*)src)[i];
    __half2* d = (__half2*)dst;
    d[2 * i]     = __floats2half2_rn(v.x, v.y);
    d[2 * i + 1] = __floats2half2_rn(v.z, v.w);
}

// ============================================================================
// transpose W_dec [IN_DIM, HID] -> g_wdecT (fp16) [HID, IN_DIM]
// ============================================================================
__global__ void wdec_transpose(const float* __restrict__ W)
{
    __shared__ float tile[32][33];
    int h0 = blockIdx.x * 32;
    int d0 = blockIdx.y * 32;
    int tx = threadIdx.x, ty = threadIdx.y;
#pragma unroll
    for (int r = 0; r < 32; r += 8)
        tile[ty + r][tx] = W[(size_t)(d0 + ty + r) * HID + (h0 + tx)];
    __syncthreads();
#pragma unroll
    for (int r = 0; r < 32; r += 8)
        g_wdecT[(size_t)(h0 + ty + r) * IN_DIM + (d0 + tx)] =
            __float2half_rn(tile[tx][ty + r]);
}

// ============================================================================
// Encoder GEMM: fp16 mma.sync (HMMA), fp32 accumulate  (unchanged — proven)
// ============================================================================
#define GBM 128
#define GBN 256
#define GBK 64
#define NSTAGE 3
#define ROWB 144
#define A_ST_B (GBM * ROWB)
#define B_ST_B (GBN * ROWB)
#define STG_B  (A_ST_B + B_ST_B)
#define GEMM_SMEM (NSTAGE * STG_B)
#define K_ITERS (IN_DIM / GBK)
#define GEMM_THREADS 512

__device__ __forceinline__ uint32_t smem_u32(const void* p) {
    uint32_t a;
    asm("{ .reg .u64 t; cvta.to.shared.u64 t, %1; cvt.u32.u64 %0, t; }" : "=r"(a) : "l"(p));
    return a;
}
#define CP_ASYNC16(dst, src) \
    asm volatile("cp.async.cg.shared.global [%0], [%1], 16;" :: "r"(dst), "l"(src))
#define CP_COMMIT() asm volatile("cp.async.commit_group;" ::: "memory")
#define CP_WAIT1()  asm volatile("cp.async.wait_group 1;" ::: "memory")

#define LDSM_X4(r0, r1, r2, r3, addr) \
    asm volatile("ldmatrix.sync.aligned.m8n8.x4.shared.b16 {%0,%1,%2,%3}, [%4];" \
                 : "=r"(r0), "=r"(r1), "=r"(r2), "=r"(r3) : "r"(addr))

#define MMA16816(d, a, b0, b1) \
    asm volatile("mma.sync.aligned.m16n8k16.row.col.f32.f16.f16.f32 " \
                 "{%0,%1,%2,%3}, {%4,%5,%6,%7}, {%8,%9}, {%0,%1,%2,%3};" \
                 : "+f"((d)[0]), "+f"((d)[1]), "+f"((d)[2]), "+f"((d)[3]) \
                 : "r"((a)[0]), "r"((a)[1]), "r"((a)[2]), "r"((a)[3]), \
                   "r"(b0), "r"(b1))

__device__ __forceinline__ void gemm_load_stage(uint32_t sbase, int stage, int k0,
                                                int m0, int n0, int tid)
{
    uint32_t sb = sbase + stage * STG_B;
#pragma unroll
    for (int t = 0; t < 2; t++) {
        int i = tid + t * GEMM_THREADS;
        int row = i >> 3, c = i & 7;
        const __half* src = g_xh + (size_t)(m0 + row) * IN_DIM + k0 + c * 8;
        CP_ASYNC16(sb + row * ROWB + c * 16, src);
    }
    uint32_t sbB = sb + A_ST_B;
#pragma unroll
    for (int t = 0; t < 4; t++) {
        int i = tid + t * GEMM_THREADS;
        int row = i >> 3, c = i & 7;
        const __half* src = g_wh + (size_t)(n0 + row) * IN_DIM + k0 + c * 8;
        CP_ASYNC16(sbB + row * ROWB + c * 16, src);
    }
}

__global__ __launch_bounds__(GEMM_THREADS, 1) void encoder_gemm_hmma(
    const float* __restrict__ bias, float* __restrict__ out_sf)
{
    extern __shared__ __align__(128) char smem[];
    uint32_t sbase = smem_u32(smem);
    const int tid  = threadIdx.x;
    const int lane = tid & 31;
    const int wid  = tid >> 5;
    const int warp_m = wid & 1;
    const int warp_n = wid >> 1;

    int pid = blockIdx.x;
    int nb = (pid >> 3) & 63;
    int mb = (pid & 7) | ((pid >> 9) << 3);
    int m0 = mb * GBM, n0 = nb * GBN;

    const int g = lane >> 3;
    const int rA = warp_m * 64 + ((g & 1) << 3) + (lane & 7);
    const int cA = (g >> 1) << 4;
    const int rB = warp_n * 32 + ((g >> 1) << 3) + (lane & 7);
    const int cB = (g & 1) << 4;

    float acc[4][4][4];
#pragma unroll
    for (int i = 0; i < 4; i++)
#pragma unroll
        for (int j = 0; j < 4; j++)
#pragma unroll
            for (int q = 0; q < 4; q++) acc[i][j][q] = 0.0f;

    gemm_load_stage(sbase, 0, 0, m0, n0, tid); CP_COMMIT();
    gemm_load_stage(sbase, 1, GBK, m0, n0, tid); CP_COMMIT();

    for (int it = 0; it < K_ITERS; it++) {
        int cur = it % 3;
        CP_WAIT1();
        __syncthreads();

        if (it + 2 < K_ITERS)
            gemm_load_stage(sbase, (it + 2) % 3, (it + 2) * GBK, m0, n0, tid);
        CP_COMMIT();

        uint32_t aST = sbase + cur * STG_B;
        uint32_t bST = aST + A_ST_B;

#pragma unroll
        for (int ks = 0; ks < 4; ks++) {
            uint32_t koff = (uint32_t)(ks * 32);
            uint32_t af[4][4], bf[2][4];
#pragma unroll
            for (int mf = 0; mf < 4; mf++) {
                uint32_t ad = aST + (uint32_t)((rA + mf * 16) * ROWB + cA) + koff;
                LDSM_X4(af[mf][0], af[mf][1], af[mf][2], af[mf][3], ad);
            }
#pragma unroll
            for (int nf = 0; nf < 2; nf++) {
                uint32_t bd = bST + (uint32_t)((rB + nf * 16) * ROWB + cB) + koff;
                LDSM_X4(bf[nf][0], bf[nf][1], bf[nf][2], bf[nf][3], bd);
            }
#pragma unroll
            for (int mf = 0; mf < 4; mf++)
#pragma unroll
                for (int nf = 0; nf < 2; nf++) {
                    MMA16816(acc[mf][nf * 2],     af[mf], bf[nf][0], bf[nf][1]);
                    MMA16816(acc[mf][nf * 2 + 1], af[mf], bf[nf][2], bf[nf][3]);
                }
        }
    }

    int rbase = m0 + warp_m * 64 + (lane >> 2);
    int cbase = n0 + warp_n * 32 + ((lane & 3) << 1);
#pragma unroll
    for (int mf = 0; mf < 4; mf++) {
#pragma unroll
        for (int nf = 0; nf < 4; nf++) {
            int col = cbase + nf * 8;
            float b0 = __ldg(&bias[col]);
            float b1 = __ldg(&bias[col + 1]);
            int r0 = rbase + mf * 16;
            float2 v0, v1;
            v0.x = fmaxf(acc[mf][nf][0] + b0, 0.0f);
            v0.y = fmaxf(acc[mf][nf][1] + b1, 0.0f);
            v1.x = fmaxf(acc[mf][nf][2] + b0, 0.0f);
            v1.y = fmaxf(acc[mf][nf][3] + b1, 0.0f);
            *(float2*)(out_sf + (size_t)r0 * HID + col)       = v0;
            *(float2*)(out_sf + (size_t)(r0 + 8) * HID + col) = v1;
        }
    }
}

// ============================================================================
// top-k (k=64): single-pass histogram bracket + exact boundary refinement
//   Conflict-free smem access throughout; ballot-built keep words.
// ============================================================================
#define TOPK_THREADS 512
#define NBINS 1024
#define TOPK_SMEM_BYTES ((HID + NBINS + HID / 32) * 4)
#define ERRB 3e-3f
#define ZCAP 128

__device__ __forceinline__ float refine_dot_warp(const float* __restrict__ xr,
                                                 const float* __restrict__ wr,
                                                 float b, int lane)
{
    float s = 0.f, c = 0.f;
    for (int t = 0; t < 16; t++) {
        int base = t * 256 + lane;
        float r = xr[base] * wr[base];
#pragma unroll
        for (int j = 1; j < 8; j++)
            r = fmaf(xr[base + 32 * j], wr[base + 32 * j], r);
        float tt = s + r;
        float z = tt - s;
        float e = (s - (tt - z)) + (r - z);
        c += e; s = tt;
    }
#pragma unroll
    for (int off = 16; off; off >>= 1) {
        float s2 = __shfl_down_sync(0xffffffffu, s, off);
        float c2 = __shfl_down_sync(0xffffffffu, c, off);
        float tt = s + s2;
        float z = tt - s;
        float e = (s - (tt - z)) + (s2 - z);
        c += c2 + e; s = tt;
    }
    float d = s + c;
    return fmaxf(d + b, 0.0f);
}

// warp 0: scan bins from top, find bin where cumulative (incl. base) reaches 64
__device__ __forceinline__ int scan_bins_top(const uint32_t* hist, int top,
                                             int base, int lane)
{
    int dbin = -1;
    int nrounds = (top + 31) / 32;
    for (int r = 0; r < nrounds; r++) {
        int bin = top - 1 - (r * 32 + lane);
        int h = (bin >= 0) ? (int)hist[bin] : 0;
        int pre = h;
#pragma unroll
        for (int off = 1; off < 32; off <<= 1) {
            int t = __shfl_up_sync(0xffffffffu, pre, off);
            if (lane >= off) pre += t;
        }
        int cum = base + pre;
        unsigned bal = __ballot_sync(0xffffffffu, (cum >= KSEL) && (bin >= 0));
        if (bal) {
            int l0 = __ffs(bal) - 1;
            dbin = top - 1 - (r * 32 + l0);
            break;
        }
        base += __shfl_sync(0xffffffffu, pre, 31);
    }
    return dbin;
}

__global__ __launch_bounds__(TOPK_THREADS) void topk_kernel(
    float* __restrict__ out_sf,
    const float* __restrict__ x,
    const float* __restrict__ W,
    const float* __restrict__ bias)
{
    extern __shared__ __align__(128) char shraw[];
    uint32_t* sbits = (uint32_t*)shraw;        // HID
    uint32_t* hist  = sbits + HID;             // NBINS
    uint32_t* keep  = sbits + HID + NBINS;     // HID/32
    __shared__ int s_big, s_nhi, s_nzone, s_dbin, s_mode;
    __shared__ int   s_zidx[ZCAP];
    __shared__ float s_zval[ZCAP];
    __shared__ unsigned char s_keepz[ZCAP];

    int row = blockIdx.x;
    int tid = threadIdx.x;
    int wid = tid >> 5, lane = tid & 31;
    float* orow = out_sf + (size_t)row * HID;

    hist[tid] = 0; hist[tid + TOPK_THREADS] = 0;
    if (tid == 0) { s_big = 0; s_nhi = 0; s_nzone = 0; s_dbin = -1; s_mode = 0; }
    __syncthreads();

    // load row (coalesced float4) + mode-A histogram on [2,8), bits[30:15]
    int mybig = 0;
#pragma unroll
    for (int t = 0; t < 8; t++) {
        int i4 = tid + t * TOPK_THREADS;
        float4 v4 = ((const float4*)orow)[i4];
        float vv[4] = {v4.x, v4.y, v4.z, v4.w};
#pragma unroll
        for (int c = 0; c < 4; c++) {
            uint32_t u = __float_as_uint(vv[c]);
            if (u == 0x80000000u) u = 0u;
            sbits[i4 * 4 + c] = u;
            float f = __uint_as_float(u);
            if (f >= 8.0f) mybig++;
            else if (f >= 2.0f) atomicAdd(&hist[(u >> 15) - 0x8000u], 1u);
        }
    }
#pragma unroll
    for (int off = 16; off; off >>= 1) mybig += __shfl_down_sync(0xffffffffu, mybig, off);
    if (lane == 0 && mybig) atomicAdd(&s_big, mybig);
    __syncthreads();

    if (wid == 0) {
        int d = scan_bins_top(hist, 512, s_big, lane);
        if (lane == 0) { s_dbin = d; if (d >= 0) s_mode = 1; }
    }
    __syncthreads();

    if (s_mode == 0) {
        // mode B (rare): histogram [0.25, 8) on bits[30:16]
        hist[tid] = 0; hist[tid + TOPK_THREADS] = 0;
        __syncthreads();
        for (int i = tid; i < HID; i += TOPK_THREADS) {
            float f = __uint_as_float(sbits[i]);
            if (f >= 0.25f && f < 8.0f)
                atomicAdd(&hist[(sbits[i] >> 16) - 0x3E80u], 1u);
        }
        __syncthreads();
        if (wid == 0) {
            int d = scan_bins_top(hist, 640, s_big, lane);
            if (lane == 0) { s_dbin = d; if (d >= 0) s_mode = 2; else s_mode = 3; }
        }
        __syncthreads();
    }

    float B_lo, B_hi;
    if (s_mode == 1) {
        B_lo = __uint_as_float((uint32_t)(0x8000u + s_dbin) << 15);
        B_hi = __uint_as_float((uint32_t)(0x8000u + s_dbin + 1) << 15);
    } else if (s_mode == 2) {
        B_lo = __uint_as_float((uint32_t)(0x3E80u + s_dbin) << 16);
        B_hi = __uint_as_float((uint32_t)(0x3E80u + s_dbin + 1) << 16);
    } else {
        B_lo = 0.0f; B_hi = 0.25f;
    }
    float Thi  = B_hi + 2.0f * ERRB;
    float Tlo  = B_lo - 2.0f * ERRB;

    // classify (conflict-free stride; warp-reduced nhi)
    {
        int myhi = 0;
        for (int i = tid; i < HID; i += TOPK_THREADS) {
            float f = __uint_as_float(sbits[i]);
            if (f > Thi) myhi++;
            else if (f > 0.0f && f >= Tlo) {
                int p = atomicAdd(&s_nzone, 1);
                if (p < ZCAP) s_zidx[p] = i;
            }
        }
#pragma unroll
        for (int off = 16; off; off >>= 1) myhi += __shfl_down_sync(0xffffffffu, myhi, off);
        if (lane == 0 && myhi) atomicAdd(&s_nhi, myhi);
    }
    __syncthreads();

    int nhi  = s_nhi;
    int nzr  = s_nzone;
    bool ovf = (nzr > ZCAP);
    int nz   = ovf ? ZCAP : nzr;
    int need = KSEL - nhi;

    if (tid < nz) s_zval[tid] = __uint_as_float(sbits[s_zidx[tid]]);
    __syncthreads();

    bool did_refine = (!ovf && nz != need && nz > 0 && need > 0);
    if (did_refine) {
        const float* xr = x + (size_t)row * IN_DIM;
        for (int j = wid; j < nz; j += (TOPK_THREADS / 32)) {
            int h = s_zidx[j];
            float v = refine_dot_warp(xr, W + (size_t)h * IN_DIM, __ldg(&bias[h]), lane);
            if (lane == 0) s_zval[j] = v;
        }
    }
    __syncthreads();

    // rank selection among zone (exact top-`need`, index tiebreak)
    if (tid < nz) {
        bool km;
        if (!ovf && nz == need) km = true;
        else if (need <= 0) km = false;
        else {
            float mv = s_zval[tid]; int mi = s_zidx[tid];
            int better = 0;
            for (int j = 0; j < nz; j++) {
                if (j == tid) continue;
                if (s_zval[j] > mv || (s_zval[j] == mv && s_zidx[j] < mi)) better++;
            }
            km = (better < need);
        }
        s_keepz[tid] = km ? 1 : 0;
    }
    __syncthreads();

    if (did_refine && tid < nz && s_keepz[tid])
        sbits[s_zidx[tid]] = __float_as_uint(s_zval[tid]);
    __syncthreads();

    // output + keep bitmap: conflict-free; ballot builds each 32-bit word
    for (int i = tid; i < HID; i += TOPK_THREADS) {
        uint32_t u = sbits[i];
        float f = __uint_as_float(u);
        bool kp = false;
        if (f > Thi) kp = true;
        else if (f > 0.0f && f >= Tlo) {
            for (int j = 0; j < nz; j++)
                if (s_zidx[j] == i) { kp = (s_keepz[j] != 0); break; }
        }
        unsigned m = __ballot_sync(0xffffffffu, kp);
        if (lane == 0) keep[i >> 5] = m;
        if (kp) orow[i] = f;
        else if (u != 0u) orow[i] = 0.0f;
    }
    __syncthreads();

    // deterministic compaction (warp 0, index order)
    if (tid < 32) {
        int cnt = 0;
        for (int base = 0; base < HID; base += 32) {
            uint32_t m = keep[base >> 5];
            bool kp = (m >> lane) & 1u;
            int r = __popc(m & ((1u << lane) - 1u));
            if (kp && cnt + r < KSEL) {
                g_vals[row * KSEL + cnt + r] = __uint_as_float(sbits[base + lane]);
                g_idx [row * KSEL + cnt + r] = base + lane;
            }
            cnt += __popc(m);
        }
    }
}

// ============================================================================
// sparse decode  recon[b,:] = sum_j v_j * W_dec^T[h_j, :]  (fp16 weights)
// ============================================================================
__global__ __launch_bounds__(256) void decoder_kernel(float* __restrict__ out_rec)
{
    int row = blockIdx.x;
    int tid = threadIdx.x;
    __shared__ float sv[KSEL];
    __shared__ int   si[KSEL];
    if (tid < KSEL) { sv[tid] = g_vals[row * KSEL + tid]; si[tid] = g_idx[row * KSEL + tid]; }
    __syncthreads();

    float acc[16];
#pragma unroll
    for (int q = 0; q < 16; q++) acc[q] = 0.0f;

    for (int j = 0; j < KSEL; j++) {
        float v = sv[j];
        const uint4* wp = (const uint4*)(g_wdecT + (size_t)si[j] * IN_DIM);
#pragma unroll
        for (int w = 0; w < 2; w++) {
            uint4 t = wp[tid + w * 256];
            float2 f0 = __half22float2(*(__half2*)&t.x);
            float2 f1 = __half22float2(*(__half2*)&t.y);
            float2 f2 = __half22float2(*(__half2*)&t.z);
            float2 f3 = __half22float2(*(__half2*)&t.w);
            acc[w*8+0] = fmaf(v, f0.x, acc[w*8+0]);
            acc[w*8+1] = fmaf(v, f0.y, acc[w*8+1]);
            acc[w*8+2] = fmaf(v, f1.x, acc[w*8+2]);
            acc[w*8+3] = fmaf(v, f1.y, acc[w*8+3]);
            acc[w*8+4] = fmaf(v, f2.x, acc[w*8+4]);
            acc[w*8+5] = fmaf(v, f2.y, acc[w*8+5]);
            acc[w*8+6] = fmaf(v, f3.x, acc[w*8+6]);
            acc[w*8+7] = fmaf(v, f3.y, acc[w*8+7]);
        }
    }
    float* op = out_rec + (size_t)row * IN_DIM;
#pragma unroll
    for (int w = 0; w < 2; w++) {
        *(float4*)(op + (tid + w * 256) * 8)     = *(float4*)(&acc[w*8]);
        *(float4*)(op + (tid + w * 256) * 8 + 4) = *(float4*)(&acc[w*8+4]);
    }
}

// ============================================================================
// launch
// ============================================================================
extern "C" void kernel_launch(void* const* d_in, const int* in_sizes, int n_in,
                              void* d_out, int out_size)
{
    const float* x     = (const float*)d_in[0];
    const float* W_enc = (const float*)d_in[1];
    const float* b_enc = (const float*)d_in[2];
    const float* W_dec = (const float*)d_in[3];

    float* out_sf  = (float*)d_out;
    float* out_rec = out_sf + (size_t)BATCH * HID;

    __half *xh, *wh;
    cudaGetSymbolAddress((void**)&xh, g_xh);
    cudaGetSymbolAddress((void**)&wh, g_wh);

    // 1) fp16 conversions
    size_t nx4 = (size_t)BATCH * IN_DIM / 4;
    size_t nw4 = (size_t)HID * IN_DIM / 4;
    to_half_kernel<<<(unsigned)(nx4 / 256), 256>>>(x, xh, nx4);
    to_half_kernel<<<(unsigned)(nw4 / 256), 256>>>(W_enc, wh, nw4);

    // 2) transpose W_dec -> fp16
    wdec_transpose<<<dim3(HID / 32, IN_DIM / 32), dim3(32, 8)>>>(W_dec);

    // 3) approx encoder GEMM (HMMA fp16, fp32 accum) -> out_sf (dense)
    cudaFuncSetAttribute(encoder_gemm_hmma, cudaFuncAttributeMaxDynamicSharedMemorySize,
                         GEMM_SMEM);
    encoder_gemm_hmma<<<(HID / GBN) * (BATCH / GBM), GEMM_THREADS, GEMM_SMEM>>>(b_enc, out_sf);

    // 4) top-k: histogram bracket + exact boundary refinement (in-place)
    cudaFuncSetAttribute(topk_kernel, cudaFuncAttributeMaxDynamicSharedMemorySize,
                         TOPK_SMEM_BYTES);
    topk_kernel<<<BATCH, TOPK_THREADS, TOPK_SMEM_BYTES>>>(out_sf, x, W_enc, b_enc);

    // 5) sparse decode (fp16 weights)
    decoder_kernel<<<BATCH, 256>>>(out_rec);
}

// round 10
// speedup vs baseline: 1.2733x; 1.1688x over previous
#include <cuda_runtime.h>
#include <cuda_fp16.h>
#include <cstdint>
#include <cstddef>

#define BATCH   8192
#define IN_DIM  4096
#define HID     16384
#define KSEL    64

// -------- scratch (allocation-free: __device__ globals) --------
__device__ __half g_wdecT[(size_t)HID * IN_DIM];     // W_dec^T in fp16 [HID, IN_DIM]
__device__ float  g_vals[BATCH * KSEL];
__device__ int    g_idx [BATCH * KSEL];
__device__ __half g_xh[(size_t)BATCH * IN_DIM];      // fp16(x)
__device__ __half g_wh[(size_t)HID * IN_DIM];        // fp16(W_enc)

// ============================================================================
// fp32 -> fp16 conversion
// ============================================================================
__global__ __launch_bounds__(256) void to_half_kernel(
    const float* __restrict__ src, __half* __restrict__ dst, size_t n4)
{
    size_t i = (size_t)blockIdx.x * 256 + threadIdx.x;
    if (i >= n4) return;
    float4 v = ((const float4*)src)[i];
    __half2* d = (__half2*)dst;
    d[2 * i]     = __floats2half2_rn(v.x, v.y);
    d[2 * i + 1] = __floats2half2_rn(v.z, v.w);
}

// ============================================================================
// transpose W_dec [IN_DIM, HID] -> g_wdecT (fp16) [HID, IN_DIM]
// ============================================================================
__global__ void wdec_transpose(const float* __restrict__ W)
{
    __shared__ float tile[32][33];
    int h0 = blockIdx.x * 32;
    int d0 = blockIdx.y * 32;
    int tx = threadIdx.x, ty = threadIdx.y;
#pragma unroll
    for (int r = 0; r < 32; r += 8)
        tile[ty + r][tx] = W[(size_t)(d0 + ty + r) * HID + (h0 + tx)];
    __syncthreads();
#pragma unroll
    for (int r = 0; r < 32; r += 8)
        g_wdecT[(size_t)(h0 + ty + r) * IN_DIM + (d0 + tx)] =
            __float2half_rn(tile[tx][ty + r]);
}

// ============================================================================
// Encoder GEMM: fp16 mma.sync (HMMA), fp32 accumulate  (unchanged — proven)
// ============================================================================
#define GBM 128
#define GBN 256
#define GBK 64
#define NSTAGE 3
#define ROWB 144
#define A_ST_B (GBM * ROWB)
#define B_ST_B (GBN * ROWB)
#define STG_B  (A_ST_B + B_ST_B)
#define GEMM_SMEM (NSTAGE * STG_B)
#define K_ITERS (IN_DIM / GBK)
#define GEMM_THREADS 512

__device__ __forceinline__ uint32_t smem_u32(const void* p) {
    uint32_t a;
    asm("{ .reg .u64 t; cvta.to.shared.u64 t, %1; cvt.u32.u64 %0, t; }" : "=r"(a) : "l"(p));
    return a;
}
#define CP_ASYNC16(dst, src) \
    asm volatile("cp.async.cg.shared.global [%0], [%1], 16;" :: "r"(dst), "l"(src))
#define CP_COMMIT() asm volatile("cp.async.commit_group;" ::: "memory")
#define CP_WAIT1()  asm volatile("cp.async.wait_group 1;" ::: "memory")

#define LDSM_X4(r0, r1, r2, r3, addr) \
    asm volatile("ldmatrix.sync.aligned.m8n8.x4.shared.b16 {%0,%1,%2,%3}, [%4];" \
                 : "=r"(r0), "=r"(r1), "=r"(r2), "=r"(r3) : "r"(addr))

#define MMA16816(d, a, b0, b1) \
    asm volatile("mma.sync.aligned.m16n8k16.row.col.f32.f16.f16.f32 " \
                 "{%0,%1,%2,%3}, {%4,%5,%6,%7}, {%8,%9}, {%0,%1,%2,%3};" \
                 : "+f"((d)[0]), "+f"((d)[1]), "+f"((d)[2]), "+f"((d)[3]) \
                 : "r"((a)[0]), "r"((a)[1]), "r"((a)[2]), "r"((a)[3]), \
                   "r"(b0), "r"(b1))

__device__ __forceinline__ void gemm_load_stage(uint32_t sbase, int stage, int k0,
                                                int m0, int n0, int tid)
{
    uint32_t sb = sbase + stage * STG_B;
#pragma unroll
    for (int t = 0; t < 2; t++) {
        int i = tid + t * GEMM_THREADS;
        int row = i >> 3, c = i & 7;
        const __half* src = g_xh + (size_t)(m0 + row) * IN_DIM + k0 + c * 8;
        CP_ASYNC16(sb + row * ROWB + c * 16, src);
    }
    uint32_t sbB = sb + A_ST_B;
#pragma unroll
    for (int t = 0; t < 4; t++) {
        int i = tid + t * GEMM_THREADS;
        int row = i >> 3, c = i & 7;
        const __half* src = g_wh + (size_t)(n0 + row) * IN_DIM + k0 + c * 8;
        CP_ASYNC16(sbB + row * ROWB + c * 16, src);
    }
}

__global__ __launch_bounds__(GEMM_THREADS, 1) void encoder_gemm_hmma(
    const float* __restrict__ bias, float* __restrict__ out_sf)
{
    extern __shared__ __align__(128) char smem[];
    uint32_t sbase = smem_u32(smem);
    const int tid  = threadIdx.x;
    const int lane = tid & 31;
    const int wid  = tid >> 5;
    const int warp_m = wid & 1;
    const int warp_n = wid >> 1;

    int pid = blockIdx.x;
    int nb = (pid >> 3) & 63;
    int mb = (pid & 7) | ((pid >> 9) << 3);
    int m0 = mb * GBM, n0 = nb * GBN;

    const int g = lane >> 3;
    const int rA = warp_m * 64 + ((g & 1) << 3) + (lane & 7);
    const int cA = (g >> 1) << 4;
    const int rB = warp_n * 32 + ((g >> 1) << 3) + (lane & 7);
    const int cB = (g & 1) << 4;

    float acc[4][4][4];
#pragma unroll
    for (int i = 0; i < 4; i++)
#pragma unroll
        for (int j = 0; j < 4; j++)
#pragma unroll
            for (int q = 0; q < 4; q++) acc[i][j][q] = 0.0f;

    gemm_load_stage(sbase, 0, 0, m0, n0, tid); CP_COMMIT();
    gemm_load_stage(sbase, 1, GBK, m0, n0, tid); CP_COMMIT();

    for (int it = 0; it < K_ITERS; it++) {
        int cur = it % 3;
        CP_WAIT1();
        __syncthreads();

        if (it + 2 < K_ITERS)
            gemm_load_stage(sbase, (it + 2) % 3, (it + 2) * GBK, m0, n0, tid);
        CP_COMMIT();

        uint32_t aST = sbase + cur * STG_B;
        uint32_t bST = aST + A_ST_B;

#pragma unroll
        for (int ks = 0; ks < 4; ks++) {
            uint32_t koff = (uint32_t)(ks * 32);
            uint32_t af[4][4], bf[2][4];
#pragma unroll
            for (int mf = 0; mf < 4; mf++) {
                uint32_t ad = aST + (uint32_t)((rA + mf * 16) * ROWB + cA) + koff;
                LDSM_X4(af[mf][0], af[mf][1], af[mf][2], af[mf][3], ad);
            }
#pragma unroll
            for (int nf = 0; nf < 2; nf++) {
                uint32_t bd = bST + (uint32_t)((rB + nf * 16) * ROWB + cB) + koff;
                LDSM_X4(bf[nf][0], bf[nf][1], bf[nf][2], bf[nf][3], bd);
            }
#pragma unroll
            for (int mf = 0; mf < 4; mf++)
#pragma unroll
                for (int nf = 0; nf < 2; nf++) {
                    MMA16816(acc[mf][nf * 2],     af[mf], bf[nf][0], bf[nf][1]);
                    MMA16816(acc[mf][nf * 2 + 1], af[mf], bf[nf][2], bf[nf][3]);
                }
        }
    }

    int rbase = m0 + warp_m * 64 + (lane >> 2);
    int cbase = n0 + warp_n * 32 + ((lane & 3) << 1);
#pragma unroll
    for (int mf = 0; mf < 4; mf++) {
#pragma unroll
        for (int nf = 0; nf < 4; nf++) {
            int col = cbase + nf * 8;
            float b0 = __ldg(&bias[col]);
            float b1 = __ldg(&bias[col + 1]);
            int r0 = rbase + mf * 16;
            float2 v0, v1;
            v0.x = fmaxf(acc[mf][nf][0] + b0, 0.0f);
            v0.y = fmaxf(acc[mf][nf][1] + b1, 0.0f);
            v1.x = fmaxf(acc[mf][nf][2] + b0, 0.0f);
            v1.y = fmaxf(acc[mf][nf][3] + b1, 0.0f);
            *(float2*)(out_sf + (size_t)r0 * HID + col)       = v0;
            *(float2*)(out_sf + (size_t)(r0 + 8) * HID + col) = v1;
        }
    }
}

// ============================================================================
// top-k v3: no smem row mirror (row stays L2-hot), static smem ~8KB,
//   4 CTAs/SM, parallel compaction. Histogram bracket + exact refinement.
// ============================================================================
#define TOPK_THREADS 512
#define NBINS 1024
#define ERRB 3e-3f
#define ZCAP 128
#define NWORDS (HID / 32)    // 512

__device__ __forceinline__ float refine_dot_warp(const float* __restrict__ xr,
                                                 const float* __restrict__ wr,
                                                 float b, int lane)
{
    float s = 0.f, c = 0.f;
    for (int t = 0; t < 16; t++) {
        int base = t * 256 + lane;
        float r = xr[base] * wr[base];
#pragma unroll
        for (int j = 1; j < 8; j++)
            r = fmaf(xr[base + 32 * j], wr[base + 32 * j], r);
        float tt = s + r;
        float z = tt - s;
        float e = (s - (tt - z)) + (r - z);
        c += e; s = tt;
    }
#pragma unroll
    for (int off = 16; off; off >>= 1) {
        float s2 = __shfl_down_sync(0xffffffffu, s, off);
        float c2 = __shfl_down_sync(0xffffffffu, c, off);
        float tt = s + s2;
        float z = tt - s;
        float e = (s - (tt - z)) + (s2 - z);
        c += c2 + e; s = tt;
    }
    float d = s + c;
    return fmaxf(d + b, 0.0f);
}

__device__ __forceinline__ int scan_bins_top(const uint32_t* hist, int top,
                                             int base, int lane)
{
    int dbin = -1;
    int nrounds = (top + 31) / 32;
    for (int r = 0; r < nrounds; r++) {
        int bin = top - 1 - (r * 32 + lane);
        int h = (bin >= 0) ? (int)hist[bin] : 0;
        int pre = h;
#pragma unroll
        for (int off = 1; off < 32; off <<= 1) {
            int t = __shfl_up_sync(0xffffffffu, pre, off);
            if (lane >= off) pre += t;
        }
        int cum = base + pre;
        unsigned bal = __ballot_sync(0xffffffffu, (cum >= KSEL) && (bin >= 0));
        if (bal) {
            int l0 = __ffs(bal) - 1;
            dbin = top - 1 - (r * 32 + l0);
            break;
        }
        base += __shfl_sync(0xffffffffu, pre, 31);
    }
    return dbin;
}

__global__ __launch_bounds__(TOPK_THREADS) void topk_kernel(
    float* __restrict__ out_sf,
    const float* __restrict__ x,
    const float* __restrict__ W,
    const float* __restrict__ bias)
{
    __shared__ uint32_t hist[NBINS];
    __shared__ uint32_t keep[NWORDS];
    __shared__ int s_big, s_nhi, s_nzone, s_dbin, s_mode;
    __shared__ int   s_zidx[ZCAP];
    __shared__ float s_zval[ZCAP];
    __shared__ unsigned char s_keepz[ZCAP];
    __shared__ int s_wsum[16];

    int row = blockIdx.x;
    int tid = threadIdx.x;
    int wid = tid >> 5, lane = tid & 31;
    float* orow = out_sf + (size_t)row * HID;

    hist[tid] = 0; hist[tid + TOPK_THREADS] = 0;
    if (tid == 0) { s_big = 0; s_nhi = 0; s_nzone = 0; s_dbin = -1; s_mode = 0; }
    __syncthreads();

    // pass 1: read row (coalesced float4, DRAM) + histogram on [2,8)
    int mybig = 0;
#pragma unroll
    for (int t = 0; t < 8; t++) {
        float4 v4 = ((const float4*)orow)[tid + t * TOPK_THREADS];
        float vv[4] = {v4.x, v4.y, v4.z, v4.w};
#pragma unroll
        for (int c = 0; c < 4; c++) {
            float f = vv[c];
            if (f >= 8.0f) mybig++;
            else if (f >= 2.0f)
                atomicAdd(&hist[(__float_as_uint(f) >> 15) - 0x8000u], 1u);
        }
    }
#pragma unroll
    for (int off = 16; off; off >>= 1) mybig += __shfl_down_sync(0xffffffffu, mybig, off);
    if (lane == 0 && mybig) atomicAdd(&s_big, mybig);
    __syncthreads();

    if (wid == 0) {
        int d = scan_bins_top(hist, 512, s_big, lane);
        if (lane == 0) { s_dbin = d; if (d >= 0) s_mode = 1; }
    }
    __syncthreads();

    if (s_mode == 0) {
        // mode B (rare): histogram [0.25, 8) on bits[30:16]
        hist[tid] = 0; hist[tid + TOPK_THREADS] = 0;
        __syncthreads();
        for (int i = tid; i < HID; i += TOPK_THREADS) {
            float f = orow[i];
            if (f >= 0.25f && f < 8.0f)
                atomicAdd(&hist[(__float_as_uint(f) >> 16) - 0x3E80u], 1u);
        }
        __syncthreads();
        if (wid == 0) {
            int d = scan_bins_top(hist, 640, s_big, lane);
            if (lane == 0) { s_dbin = d; if (d >= 0) s_mode = 2; else s_mode = 3; }
        }
        __syncthreads();
    }

    float B_lo, B_hi;
    if (s_mode == 1) {
        B_lo = __uint_as_float((uint32_t)(0x8000u + s_dbin) << 15);
        B_hi = __uint_as_float((uint32_t)(0x8000u + s_dbin + 1) << 15);
    } else if (s_mode == 2) {
        B_lo = __uint_as_float((uint32_t)(0x3E80u + s_dbin) << 16);
        B_hi = __uint_as_float((uint32_t)(0x3E80u + s_dbin + 1) << 16);
    } else {
        B_lo = 0.0f; B_hi = 0.25f;
    }
    float Thi = B_hi + 2.0f * ERRB;
    float Tlo = B_lo - 2.0f * ERRB;

    // pass 2: classify (L2-hot reread)
    {
        int myhi = 0;
#pragma unroll
        for (int t = 0; t < 8; t++) {
            int i4 = tid + t * TOPK_THREADS;
            float4 v4 = ((const float4*)orow)[i4];
            float vv[4] = {v4.x, v4.y, v4.z, v4.w};
#pragma unroll
            for (int c = 0; c < 4; c++) {
                float f = vv[c];
                if (f > Thi) myhi++;
                else if (f > 0.0f && f >= Tlo) {
                    int p = atomicAdd(&s_nzone, 1);
                    if (p < ZCAP) s_zidx[p] = i4 * 4 + c;
                }
            }
        }
#pragma unroll
        for (int off = 16; off; off >>= 1) myhi += __shfl_down_sync(0xffffffffu, myhi, off);
        if (lane == 0 && myhi) atomicAdd(&s_nhi, myhi);
    }
    __syncthreads();

    int nhi  = s_nhi;
    int nzr  = s_nzone;
    bool ovf = (nzr > ZCAP);
    int nz   = ovf ? ZCAP : nzr;
    int need = KSEL - nhi;

    if (tid < nz) s_zval[tid] = orow[s_zidx[tid]];
    __syncthreads();

    bool did_refine = (!ovf && nz != need && nz > 0 && need > 0);
    if (did_refine) {
        const float* xr = x + (size_t)row * IN_DIM;
        for (int j = wid; j < nz; j += (TOPK_THREADS / 32)) {
            int h = s_zidx[j];
            float v = refine_dot_warp(xr, W + (size_t)h * IN_DIM, __ldg(&bias[h]), lane);
            if (lane == 0) s_zval[j] = v;
        }
    }
    __syncthreads();

    // rank selection among zone (exact top-`need`, index tiebreak)
    if (tid < nz) {
        bool km;
        if (!ovf && nz == need) km = true;
        else if (need <= 0) km = false;
        else {
            float mv = s_zval[tid]; int mi = s_zidx[tid];
            int better = 0;
            for (int j = 0; j < nz; j++) {
                if (j == tid) continue;
                if (s_zval[j] > mv || (s_zval[j] == mv && s_zidx[j] < mi)) better++;
            }
            km = (better < need);
        }
        s_keepz[tid] = km ? 1 : 0;
    }
    __syncthreads();

    // pass 3: output + ballot keep words (each warp owns contiguous 32-elt words)
    for (int w = wid; w < NWORDS; w += (TOPK_THREADS / 32)) {
        int i = w * 32 + lane;
        float f = orow[i];
        bool kp = false;
        float outv = f;
        if (f > Thi) kp = true;
        else if (f > 0.0f && f >= Tlo) {
            for (int j = 0; j < nz; j++)
                if (s_zidx[j] == i) {
                    kp = (s_keepz[j] != 0);
                    if (kp && did_refine) outv = s_zval[j];
                    break;
                }
        }
        unsigned m = __ballot_sync(0xffffffffu, kp);
        if (lane == 0) keep[w] = m;
        if (kp) { if (outv != f) orow[i] = outv; }
        else if (__float_as_uint(f) != 0u) orow[i] = 0.0f;
    }
    __syncthreads();

    // parallel compaction: block exclusive scan over keep-word popcounts
    {
        uint32_t m = keep[tid];
        int c = __popc(m);
        int pre = c;
#pragma unroll
        for (int off = 1; off < 32; off <<= 1) {
            int t = __shfl_up_sync(0xffffffffu, pre, off);
            if (lane >= off) pre += t;
        }
        if (lane == 31) s_wsum[wid] = pre;
        __syncthreads();
        if (wid == 0 && lane < 16) {
            int v = s_wsum[lane];
            int p = v;
#pragma unroll
            for (int off = 1; off < 16; off <<= 1) {
                int t = __shfl_up_sync(0xffffu, p, off);
                if (lane >= off) p += t;
            }
            s_wsum[lane] = p - v;   // exclusive warp-base
        }
        __syncthreads();
        int excl = s_wsum[wid] + pre - c;
        while (m) {
            int b = __ffs(m) - 1;
            m &= m - 1;
            if (excl < KSEL) {
                g_vals[row * KSEL + excl] = orow[tid * 32 + b];
                g_idx [row * KSEL + excl] = tid * 32 + b;
            }
            excl++;
        }
    }
}

// ============================================================================
// sparse decode  recon[b,:] = sum_j v_j * W_dec^T[h_j, :]  (fp16 weights)
// ============================================================================
__global__ __launch_bounds__(256) void decoder_kernel(float* __restrict__ out_rec)
{
    int row = blockIdx.x;
    int tid = threadIdx.x;
    __shared__ float sv[KSEL];
    __shared__ int   si[KSEL];
    if (tid < KSEL) { sv[tid] = g_vals[row * KSEL + tid]; si[tid] = g_idx[row * KSEL + tid]; }
    __syncthreads();

    float acc[16];
#pragma unroll
    for (int q = 0; q < 16; q++) acc[q] = 0.0f;

    for (int j = 0; j < KSEL; j++) {
        float v = sv[j];
        const uint4* wp = (const uint4*)(g_wdecT + (size_t)si[j] * IN_DIM);
#pragma unroll
        for (int w = 0; w < 2; w++) {
            uint4 t = wp[tid + w * 256];
            float2 f0 = __half22float2(*(__half2*)&t.x);
            float2 f1 = __half22float2(*(__half2*)&t.y);
            float2 f2 = __half22float2(*(__half2*)&t.z);
            float2 f3 = __half22float2(*(__half2*)&t.w);
            acc[w*8+0] = fmaf(v, f0.x, acc[w*8+0]);
            acc[w*8+1] = fmaf(v, f0.y, acc[w*8+1]);
            acc[w*8+2] = fmaf(v, f1.x, acc[w*8+2]);
            acc[w*8+3] = fmaf(v, f1.y, acc[w*8+3]);
            acc[w*8+4] = fmaf(v, f2.x, acc[w*8+4]);
            acc[w*8+5] = fmaf(v, f2.y, acc[w*8+5]);
            acc[w*8+6] = fmaf(v, f3.x, acc[w*8+6]);
            acc[w*8+7] = fmaf(v, f3.y, acc[w*8+7]);
        }
    }
    float* op = out_rec + (size_t)row * IN_DIM;
#pragma unroll
    for (int w = 0; w < 2; w++) {
        *(float4*)(op + (tid + w * 256) * 8)     = *(float4*)(&acc[w*8]);
        *(float4*)(op + (tid + w * 256) * 8 + 4) = *(float4*)(&acc[w*8+4]);
    }
}

// ============================================================================
// launch
// ============================================================================
extern "C" void kernel_launch(void* const* d_in, const int* in_sizes, int n_in,
                              void* d_out, int out_size)
{
    const float* x     = (const float*)d_in[0];
    const float* W_enc = (const float*)d_in[1];
    const float* b_enc = (const float*)d_in[2];
    const float* W_dec = (const float*)d_in[3];

    float* out_sf  = (float*)d_out;
    float* out_rec = out_sf + (size_t)BATCH * HID;

    __half *xh, *wh;
    cudaGetSymbolAddress((void**)&xh, g_xh);
    cudaGetSymbolAddress((void**)&wh, g_wh);

    // 1) fp16 conversions
    size_t nx4 = (size_t)BATCH * IN_DIM / 4;
    size_t nw4 = (size_t)HID * IN_DIM / 4;
    to_half_kernel<<<(unsigned)(nx4 / 256), 256>>>(x, xh, nx4);
    to_half_kernel<<<(unsigned)(nw4 / 256), 256>>>(W_enc, wh, nw4);

    // 2) transpose W_dec -> fp16
    wdec_transpose<<<dim3(HID / 32, IN_DIM / 32), dim3(32, 8)>>>(W_dec);

    // 3) approx encoder GEMM (HMMA fp16, fp32 accum) -> out_sf (dense)
    cudaFuncSetAttribute(encoder_gemm_hmma, cudaFuncAttributeMaxDynamicSharedMemorySize,
                         GEMM_SMEM);
    encoder_gemm_hmma<<<(HID / GBN) * (BATCH / GBM), GEMM_THREADS, GEMM_SMEM>>>(b_enc, out_sf);

    // 4) top-k v3: L2-resident row, static smem, parallel compaction
    topk_kernel<<<BATCH, TOPK_THREADS>>>(out_sf, x, W_enc, b_enc);

    // 5) sparse decode (fp16 weights)
    decoder_kernel<<<BATCH, 256>>>(out_rec);
}

// round 11
// speedup vs baseline: 1.2834x; 1.0080x over previous
#include <cuda_runtime.h>
#include <cuda_fp16.h>
#include <cstdint>
#include <cstddef>

#define BATCH   8192
#define IN_DIM  4096
#define HID     16384
#define KSEL    64

// -------- scratch (allocation-free: __device__ globals) --------
__device__ __half g_wdecT[(size_t)HID * IN_DIM];     // W_dec^T in fp16 [HID, IN_DIM]
__device__ float  g_vals[BATCH * KSEL];
__device__ int    g_idx [BATCH * KSEL];
__device__ __half g_xh[(size_t)BATCH * IN_DIM];      // fp16(x)
__device__ __half g_wh[(size_t)HID * IN_DIM];        // fp16(W_enc)

// ============================================================================
// fp32 -> fp16 conversion
// ============================================================================
__global__ __launch_bounds__(256) void to_half_kernel(
    const float* __restrict__ src, __half* __restrict__ dst, size_t n4)
{
    size_t i = (size_t)blockIdx.x * 256 + threadIdx.x;
    if (i >= n4) return;
    float4 v = ((const float4*)src)[i];
    __half2* d = (__half2*)dst;
    d[2 * i]     = __floats2half2_rn(v.x, v.y);
    d[2 * i + 1] = __floats2half2_rn(v.z, v.w);
}

// ============================================================================
// transpose W_dec [IN_DIM, HID] -> g_wdecT (fp16) [HID, IN_DIM]
// ============================================================================
__global__ void wdec_transpose(const float* __restrict__ W)
{
    __shared__ float tile[32][33];
    int h0 = blockIdx.x * 32;
    int d0 = blockIdx.y * 32;
    int tx = threadIdx.x, ty = threadIdx.y;
#pragma unroll
    for (int r = 0; r < 32; r += 8)
        tile[ty + r][tx] = W[(size_t)(d0 + ty + r) * HID + (h0 + tx)];
    __syncthreads();
#pragma unroll
    for (int r = 0; r < 32; r += 8)
        g_wdecT[(size_t)(h0 + ty + r) * IN_DIM + (d0 + tx)] =
            __float2half_rn(tile[tx][ty + r]);
}

// ============================================================================
// Encoder GEMM: fp16 mma.sync (HMMA), fp32 accumulate
//   BM=128, BN=128, BK=64, 8 warps (2x4), warp tile 64x32,
//   3-stage cp.async, 2 CTAs/SM (110.6 KB smem each) for cross-CTA overlap.
// ============================================================================
#define GBM 128
#define GBN 128
#define GBK 64
#define NSTAGE 3
#define ROWB 144
#define A_ST_B (GBM * ROWB)          // 18432
#define B_ST_B (GBN * ROWB)          // 18432
#define STG_B  (A_ST_B + B_ST_B)     // 36864
#define GEMM_SMEM (NSTAGE * STG_B)   // 110592
#define K_ITERS (IN_DIM / GBK)       // 64
#define GEMM_THREADS 256

__device__ __forceinline__ uint32_t smem_u32(const void* p) {
    uint32_t a;
    asm("{ .reg .u64 t; cvta.to.shared.u64 t, %1; cvt.u32.u64 %0, t; }" : "=r"(a) : "l"(p));
    return a;
}
#define CP_ASYNC16(dst, src) \
    asm volatile("cp.async.cg.shared.global [%0], [%1], 16;" :: "r"(dst), "l"(src))
#define CP_COMMIT() asm volatile("cp.async.commit_group;" ::: "memory")
#define CP_WAIT1()  asm volatile("cp.async.wait_group 1;" ::: "memory")

#define LDSM_X4(r0, r1, r2, r3, addr) \
    asm volatile("ldmatrix.sync.aligned.m8n8.x4.shared.b16 {%0,%1,%2,%3}, [%4];" \
                 : "=r"(r0), "=r"(r1), "=r"(r2), "=r"(r3) : "r"(addr))

#define MMA16816(d, a, b0, b1) \
    asm volatile("mma.sync.aligned.m16n8k16.row.col.f32.f16.f16.f32 " \
                 "{%0,%1,%2,%3}, {%4,%5,%6,%7}, {%8,%9}, {%0,%1,%2,%3};" \
                 : "+f"((d)[0]), "+f"((d)[1]), "+f"((d)[2]), "+f"((d)[3]) \
                 : "r"((a)[0]), "r"((a)[1]), "r"((a)[2]), "r"((a)[3]), \
                   "r"(b0), "r"(b1))

__device__ __forceinline__ void gemm_load_stage(uint32_t sbase, int stage, int k0,
                                                int m0, int n0, int tid)
{
    uint32_t sb = sbase + stage * STG_B;
    // A: 128 rows x 8 chunks of 16B = 1024 cp.async / 256 threads
#pragma unroll
    for (int t = 0; t < 4; t++) {
        int i = tid + t * GEMM_THREADS;
        int row = i >> 3, c = i & 7;
        const __half* src = g_xh + (size_t)(m0 + row) * IN_DIM + k0 + c * 8;
        CP_ASYNC16(sb + row * ROWB + c * 16, src);
    }
    uint32_t sbB = sb + A_ST_B;
#pragma unroll
    for (int t = 0; t < 4; t++) {
        int i = tid + t * GEMM_THREADS;
        int row = i >> 3, c = i & 7;
        const __half* src = g_wh + (size_t)(n0 + row) * IN_DIM + k0 + c * 8;
        CP_ASYNC16(sbB + row * ROWB + c * 16, src);
    }
}

__global__ __launch_bounds__(GEMM_THREADS, 2) void encoder_gemm_hmma(
    const float* __restrict__ bias, float* __restrict__ out_sf)
{
    extern __shared__ __align__(128) char smem[];
    uint32_t sbase = smem_u32(smem);
    const int tid  = threadIdx.x;
    const int lane = tid & 31;
    const int wid  = tid >> 5;
    const int warp_m = wid & 1;       // 0..1 -> 64-row half
    const int warp_n = wid >> 1;      // 0..3 -> 32-col slice

    // supertile swizzle: 8 consecutive CTAs share one B tile (same nb)
    int pid = blockIdx.x;
    int nb = (pid >> 3) & 127;
    int mb = (pid & 7) | ((pid >> 10) << 3);
    int m0 = mb * GBM, n0 = nb * GBN;

    const int g = lane >> 3;
    const int rA = warp_m * 64 + ((g & 1) << 3) + (lane & 7);
    const int cA = (g >> 1) << 4;
    const int rB = warp_n * 32 + ((g >> 1) << 3) + (lane & 7);
    const int cB = (g & 1) << 4;

    float acc[4][4][4];
#pragma unroll
    for (int i = 0; i < 4; i++)
#pragma unroll
        for (int j = 0; j < 4; j++)
#pragma unroll
            for (int q = 0; q < 4; q++) acc[i][j][q] = 0.0f;

    gemm_load_stage(sbase, 0, 0, m0, n0, tid); CP_COMMIT();
    gemm_load_stage(sbase, 1, GBK, m0, n0, tid); CP_COMMIT();

    for (int it = 0; it < K_ITERS; it++) {
        int cur = it % 3;
        CP_WAIT1();
        __syncthreads();

        if (it + 2 < K_ITERS)
            gemm_load_stage(sbase, (it + 2) % 3, (it + 2) * GBK, m0, n0, tid);
        CP_COMMIT();

        uint32_t aST = sbase + cur * STG_B;
        uint32_t bST = aST + A_ST_B;

#pragma unroll
        for (int ks = 0; ks < 4; ks++) {
            uint32_t koff = (uint32_t)(ks * 32);
            uint32_t af[4][4], bf[2][4];
#pragma unroll
            for (int mf = 0; mf < 4; mf++) {
                uint32_t ad = aST + (uint32_t)((rA + mf * 16) * ROWB + cA) + koff;
                LDSM_X4(af[mf][0], af[mf][1], af[mf][2], af[mf][3], ad);
            }
#pragma unroll
            for (int nf = 0; nf < 2; nf++) {
                uint32_t bd = bST + (uint32_t)((rB + nf * 16) * ROWB + cB) + koff;
                LDSM_X4(bf[nf][0], bf[nf][1], bf[nf][2], bf[nf][3], bd);
            }
#pragma unroll
            for (int mf = 0; mf < 4; mf++)
#pragma unroll
                for (int nf = 0; nf < 2; nf++) {
                    MMA16816(acc[mf][nf * 2],     af[mf], bf[nf][0], bf[nf][1]);
                    MMA16816(acc[mf][nf * 2 + 1], af[mf], bf[nf][2], bf[nf][3]);
                }
        }
    }

    int rbase = m0 + warp_m * 64 + (lane >> 2);
    int cbase = n0 + warp_n * 32 + ((lane & 3) << 1);
#pragma unroll
    for (int mf = 0; mf < 4; mf++) {
#pragma unroll
        for (int nf = 0; nf < 4; nf++) {
            int col = cbase + nf * 8;
            float b0 = __ldg(&bias[col]);
            float b1 = __ldg(&bias[col + 1]);
            int r0 = rbase + mf * 16;
            float2 v0, v1;
            v0.x = fmaxf(acc[mf][nf][0] + b0, 0.0f);
            v0.y = fmaxf(acc[mf][nf][1] + b1, 0.0f);
            v1.x = fmaxf(acc[mf][nf][2] + b0, 0.0f);
            v1.y = fmaxf(acc[mf][nf][3] + b1, 0.0f);
            *(float2*)(out_sf + (size_t)r0 * HID + col)       = v0;
            *(float2*)(out_sf + (size_t)(r0 + 8) * HID + col) = v1;
        }
    }
}

// ============================================================================
// top-k v4: 2 sweeps (hist; classify+output+provisional-keep), zone patching
//   via atomicOr. L2-resident row, ~8KB static smem, parallel compaction.
// ============================================================================
#define TOPK_THREADS 512
#define NBINS 1024
#define ERRB 3e-3f
#define ZCAP 128
#define NWORDS (HID / 32)    // 512

__device__ __forceinline__ float refine_dot_warp(const float* __restrict__ xr,
                                                 const float* __restrict__ wr,
                                                 float b, int lane)
{
    float s = 0.f, c = 0.f;
    for (int t = 0; t < 16; t++) {
        int base = t * 256 + lane;
        float r = xr[base] * wr[base];
#pragma unroll
        for (int j = 1; j < 8; j++)
            r = fmaf(xr[base + 32 * j], wr[base + 32 * j], r);
        float tt = s + r;
        float z = tt - s;
        float e = (s - (tt - z)) + (r - z);
        c += e; s = tt;
    }
#pragma unroll
    for (int off = 16; off; off >>= 1) {
        float s2 = __shfl_down_sync(0xffffffffu, s, off);
        float c2 = __shfl_down_sync(0xffffffffu, c, off);
        float tt = s + s2;
        float z = tt - s;
        float e = (s - (tt - z)) + (s2 - z);
        c += c2 + e; s = tt;
    }
    float d = s + c;
    return fmaxf(d + b, 0.0f);
}

__device__ __forceinline__ int scan_bins_top(const uint32_t* hist, int top,
                                             int base, int lane)
{
    int dbin = -1;
    int nrounds = (top + 31) / 32;
    for (int r = 0; r < nrounds; r++) {
        int bin = top - 1 - (r * 32 + lane);
        int h = (bin >= 0) ? (int)hist[bin] : 0;
        int pre = h;
#pragma unroll
        for (int off = 1; off < 32; off <<= 1) {
            int t = __shfl_up_sync(0xffffffffu, pre, off);
            if (lane >= off) pre += t;
        }
        int cum = base + pre;
        unsigned bal = __ballot_sync(0xffffffffu, (cum >= KSEL) && (bin >= 0));
        if (bal) {
            int l0 = __ffs(bal) - 1;
            dbin = top - 1 - (r * 32 + l0);
            break;
        }
        base += __shfl_sync(0xffffffffu, pre, 31);
    }
    return dbin;
}

__global__ __launch_bounds__(TOPK_THREADS) void topk_kernel(
    float* __restrict__ out_sf,
    const float* __restrict__ x,
    const float* __restrict__ W,
    const float* __restrict__ bias)
{
    __shared__ uint32_t hist[NBINS];
    __shared__ uint32_t keep[NWORDS];
    __shared__ int s_big, s_nhi, s_nzone, s_dbin, s_mode;
    __shared__ int   s_zidx[ZCAP];
    __shared__ float s_zval[ZCAP];
    __shared__ unsigned char s_keepz[ZCAP];
    __shared__ int s_wsum[16];

    int row = blockIdx.x;
    int tid = threadIdx.x;
    int wid = tid >> 5, lane = tid & 31;
    float* orow = out_sf + (size_t)row * HID;

    hist[tid] = 0; hist[tid + TOPK_THREADS] = 0;
    if (tid == 0) { s_big = 0; s_nhi = 0; s_nzone = 0; s_dbin = -1; s_mode = 0; }
    __syncthreads();

    // sweep 1: read row (coalesced float4, DRAM) + histogram on [2,8)
    int mybig = 0;
#pragma unroll
    for (int t = 0; t < 8; t++) {
        float4 v4 = ((const float4*)orow)[tid + t * TOPK_THREADS];
        float vv[4] = {v4.x, v4.y, v4.z, v4.w};
#pragma unroll
        for (int c = 0; c < 4; c++) {
            float f = vv[c];
            if (f >= 8.0f) mybig++;
            else if (f >= 2.0f)
                atomicAdd(&hist[(__float_as_uint(f) >> 15) - 0x8000u], 1u);
        }
    }
#pragma unroll
    for (int off = 16; off; off >>= 1) mybig += __shfl_down_sync(0xffffffffu, mybig, off);
    if (lane == 0 && mybig) atomicAdd(&s_big, mybig);
    __syncthreads();

    if (wid == 0) {
        int d = scan_bins_top(hist, 512, s_big, lane);
        if (lane == 0) { s_dbin = d; if (d >= 0) s_mode = 1; }
    }
    __syncthreads();

    if (s_mode == 0) {
        // mode B (rare): histogram [0.25, 8) on bits[30:16]
        hist[tid] = 0; hist[tid + TOPK_THREADS] = 0;
        __syncthreads();
        for (int i = tid; i < HID; i += TOPK_THREADS) {
            float f = orow[i];
            if (f >= 0.25f && f < 8.0f)
                atomicAdd(&hist[(__float_as_uint(f) >> 16) - 0x3E80u], 1u);
        }
        __syncthreads();
        if (wid == 0) {
            int d = scan_bins_top(hist, 640, s_big, lane);
            if (lane == 0) { s_dbin = d; if (d >= 0) s_mode = 2; else s_mode = 3; }
        }
        __syncthreads();
    }

    float B_lo, B_hi;
    if (s_mode == 1) {
        B_lo = __uint_as_float((uint32_t)(0x8000u + s_dbin) << 15);
        B_hi = __uint_as_float((uint32_t)(0x8000u + s_dbin + 1) << 15);
    } else if (s_mode == 2) {
        B_lo = __uint_as_float((uint32_t)(0x3E80u + s_dbin) << 16);
        B_hi = __uint_as_float((uint32_t)(0x3E80u + s_dbin + 1) << 16);
    } else {
        B_lo = 0.0f; B_hi = 0.25f;
    }
    float Thi = B_hi + 2.0f * ERRB;
    float Tlo = B_lo - 2.0f * ERRB;

    // sweep 2 (L2-hot): classify + zero below-zone positives + provisional keep
    {
        int myhi = 0;
        for (int w = wid; w < NWORDS; w += (TOPK_THREADS / 32)) {
            int i = w * 32 + lane;
            float f = orow[i];
            bool hi = (f > Thi);
            bool inz = false;
            if (!hi && f > 0.0f && f >= Tlo) {
                int p = atomicAdd(&s_nzone, 1);
                if (p < ZCAP) { s_zidx[p] = i; s_zval[p] = f; inz = true; }
            }
            myhi += hi;
            unsigned m = __ballot_sync(0xffffffffu, hi);
            if (lane == 0) keep[w] = m;
            // zero all positives that are neither definite-keep nor recorded zone
            if (!hi && !inz && __float_as_uint(f) != 0u) orow[i] = 0.0f;
        }
#pragma unroll
        for (int off = 16; off; off >>= 1) myhi += __shfl_down_sync(0xffffffffu, myhi, off);
        if (lane == 0 && myhi) atomicAdd(&s_nhi, myhi);
    }
    __syncthreads();

    int nhi  = s_nhi;
    int nzr  = s_nzone;
    bool ovf = (nzr > ZCAP);
    int nz   = ovf ? ZCAP : nzr;
    int need = KSEL - nhi;

    bool did_refine = (!ovf && nz != need && nz > 0 && need > 0);
    if (did_refine) {
        const float* xr = x + (size_t)row * IN_DIM;
        for (int j = wid; j < nz; j += (TOPK_THREADS / 32)) {
            int h = s_zidx[j];
            float v = refine_dot_warp(xr, W + (size_t)h * IN_DIM, __ldg(&bias[h]), lane);
            if (lane == 0) s_zval[j] = v;
        }
    }
    __syncthreads();

    // rank selection among zone (exact top-`need`, index tiebreak)
    if (tid < nz) {
        bool km;
        if (!ovf && nz == need) km = true;
        else if (need <= 0) km = false;
        else {
            float mv = s_zval[tid]; int mi = s_zidx[tid];
            int better = 0;
            for (int j = 0; j < nz; j++) {
                if (j == tid) continue;
                if (s_zval[j] > mv || (s_zval[j] == mv && s_zidx[j] < mi)) better++;
            }
            km = (better < need);
        }
        s_keepz[tid] = km ? 1 : 0;
    }
    __syncthreads();

    // patch zone elements: kept -> (refined) value + keep bit; dropped -> 0
    if (tid < nz) {
        int i = s_zidx[tid];
        if (s_keepz[tid]) {
            orow[i] = s_zval[tid];                 // refined (or approx) value
            atomicOr(&keep[i >> 5], 1u << (i & 31));
        } else {
            orow[i] = 0.0f;
        }
    }
    __syncthreads();

    // parallel compaction: block exclusive scan over keep-word popcounts
    {
        uint32_t m = keep[tid];
        int c = __popc(m);
        int pre = c;
#pragma unroll
        for (int off = 1; off < 32; off <<= 1) {
            int t = __shfl_up_sync(0xffffffffu, pre, off);
            if (lane >= off) pre += t;
        }
        if (lane == 31) s_wsum[wid] = pre;
        __syncthreads();
        if (wid == 0 && lane < 16) {
            int v = s_wsum[lane];
            int p = v;
#pragma unroll
            for (int off = 1; off < 16; off <<= 1) {
                int t = __shfl_up_sync(0xffffu, p, off);
                if (lane >= off) p += t;
            }
            s_wsum[lane] = p - v;   // exclusive warp-base
        }
        __syncthreads();
        int excl = s_wsum[wid] + pre - c;
        while (m) {
            int b = __ffs(m) - 1;
            m &= m - 1;
            if (excl < KSEL) {
                g_vals[row * KSEL + excl] = orow[tid * 32 + b];
                g_idx [row * KSEL + excl] = tid * 32 + b;
            }
            excl++;
        }
    }
}

// ============================================================================
// sparse decode  recon[b,:] = sum_j v_j * W_dec^T[h_j, :]  (fp16 weights)
// ============================================================================
__global__ __launch_bounds__(256) void decoder_kernel(float* __restrict__ out_rec)
{
    int row = blockIdx.x;
    int tid = threadIdx.x;
    __shared__ float sv[KSEL];
    __shared__ int   si[KSEL];
    if (tid < KSEL) { sv[tid] = g_vals[row * KSEL + tid]; si[tid] = g_idx[row * KSEL + tid]; }
    __syncthreads();

    float acc[16];
#pragma unroll
    for (int q = 0; q < 16; q++) acc[q] = 0.0f;

    for (int j = 0; j < KSEL; j++) {
        float v = sv[j];
        const uint4* wp = (const uint4*)(g_wdecT + (size_t)si[j] * IN_DIM);
#pragma unroll
        for (int w = 0; w < 2; w++) {
            uint4 t = wp[tid + w * 256];
            float2 f0 = __half22float2(*(__half2*)&t.x);
            float2 f1 = __half22float2(*(__half2*)&t.y);
            float2 f2 = __half22float2(*(__half2*)&t.z);
            float2 f3 = __half22float2(*(__half2*)&t.w);
            acc[w*8+0] = fmaf(v, f0.x, acc[w*8+0]);
            acc[w*8+1] = fmaf(v, f0.y, acc[w*8+1]);
            acc[w*8+2] = fmaf(v, f1.x, acc[w*8+2]);
            acc[w*8+3] = fmaf(v, f1.y, acc[w*8+3]);
            acc[w*8+4] = fmaf(v, f2.x, acc[w*8+4]);
            acc[w*8+5] = fmaf(v, f2.y, acc[w*8+5]);
            acc[w*8+6] = fmaf(v, f3.x, acc[w*8+6]);
            acc[w*8+7] = fmaf(v, f3.y, acc[w*8+7]);
        }
    }
    float* op = out_rec + (size_t)row * IN_DIM;
#pragma unroll
    for (int w = 0; w < 2; w++) {
        *(float4*)(op + (tid + w * 256) * 8)     = *(float4*)(&acc[w*8]);
        *(float4*)(op + (tid + w * 256) * 8 + 4) = *(float4*)(&acc[w*8+4]);
    }
}

// ============================================================================
// launch
// ============================================================================
extern "C" void kernel_launch(void* const* d_in, const int* in_sizes, int n_in,
                              void* d_out, int out_size)
{
    const float* x     = (const float*)d_in[0];
    const float* W_enc = (const float*)d_in[1];
    const float* b_enc = (const float*)d_in[2];
    const float* W_dec = (const float*)d_in[3];

    float* out_sf  = (float*)d_out;
    float* out_rec = out_sf + (size_t)BATCH * HID;

    __half *xh, *wh;
    cudaGetSymbolAddress((void**)&xh, g_xh);
    cudaGetSymbolAddress((void**)&wh, g_wh);

    // 1) fp16 conversions
    size_t nx4 = (size_t)BATCH * IN_DIM / 4;
    size_t nw4 = (size_t)HID * IN_DIM / 4;
    to_half_kernel<<<(unsigned)(nx4 / 256), 256>>>(x, xh, nx4);
    to_half_kernel<<<(unsigned)(nw4 / 256), 256>>>(W_enc, wh, nw4);

    // 2) transpose W_dec -> fp16
    wdec_transpose<<<dim3(HID / 32, IN_DIM / 32), dim3(32, 8)>>>(W_dec);

    // 3) approx encoder GEMM (HMMA fp16, fp32 accum, 2 CTAs/SM) -> out_sf
    cudaFuncSetAttribute(encoder_gemm_hmma, cudaFuncAttributeMaxDynamicSharedMemorySize,
                         GEMM_SMEM);
    encoder_gemm_hmma<<<(HID / GBN) * (BATCH / GBM), GEMM_THREADS, GEMM_SMEM>>>(b_enc, out_sf);

    // 4) top-k v4: 2-sweep bracket + exact boundary refinement (in-place)
    topk_kernel<<<BATCH, TOPK_THREADS>>>(out_sf, x, W_enc, b_enc);

    // 5) sparse decode (fp16 weights)
    decoder_kernel<<<BATCH, 256>>>(out_rec);
}